// round 7
// baseline (speedup 1.0000x reference)
#include <cuda_runtime.h>
#include <cuda_bf16.h>
#include <cstdint>

// LocallyConnected2d via single-pass tf32 mma.sync m16n8k8 implicit GEMM with
// cp.async double-buffered staging.
// out[b,o,h,w] = sum_{c,k} patch(x)[b,c,h,w,k] * W[o,c,h,w,k]
// x: [128,64,32,32] f32   weight: [1,64,64,32,32,9] f32   out: [128,64,32,32] f32
//
// R7: incremental B-staging pointers (kill per-cp4 /9 address math),
//     BSTR 72->76 floats (B lds64 2 wf, was 4), A b-paired layout so A frags
//     are lds64 (half the LDS instructions).

#define BATCH 128
#define CI    64
#define CO    64
#define HGT   32
#define WID   32
#define HWN   1024
#define KC    64
#define NCHUNK 9

#define ASTRB 544                   // A row stride bytes (136 floats)
#define BSTRB 304                   // B row stride bytes (76 floats)
#define OFF_B 34816                 // 64*544
#define STAGE 54272                 // 34816 + 64*304
#define DYN_BYTES (2 * STAGE)

__device__ float g_xT[CI * HGT * WID * BATCH];   // 16 MB [c][h][w][pairperm(b)], tf32-rounded
__device__ float g_outT[HWN * CO * BATCH];       // 32 MB [hw][o][b]

// ---------------- helpers ----------------------------------------------------
__device__ __forceinline__ uint32_t smem_u32(const void* p) {
    uint32_t a;
    asm("{ .reg .u64 t; cvta.to.shared.u64 t, %1; cvt.u32.u64 %0, t; }" : "=r"(a) : "l"(p));
    return a;
}
__device__ __forceinline__ float f2tf32(float v) {
    uint32_t r; asm("cvt.rna.tf32.f32 %0, %1;" : "=r"(r) : "f"(v));
    return __uint_as_float(r);
}
__device__ __forceinline__ void lds64(uint32_t a, uint32_t& lo, uint32_t& hi) {
    asm volatile("ld.shared.v2.b32 {%0,%1}, [%2];" : "=r"(lo), "=r"(hi) : "r"(a));
}
__device__ __forceinline__ void cp16(uint32_t dst, const void* src, int srcbytes) {
    asm volatile("cp.async.cg.shared.global [%0], [%1], 16, %2;"
                 :: "r"(dst), "l"(src), "r"(srcbytes) : "memory");
}
__device__ __forceinline__ void cp4(uint32_t dst, const void* src) {
    asm volatile("cp.async.ca.shared.global [%0], [%1], 4;"
                 :: "r"(dst), "l"(src) : "memory");
}
#define CP_COMMIT() asm volatile("cp.async.commit_group;" ::: "memory")
__device__ __forceinline__ void mma_tf32(float* d, const uint32_t* a, const uint32_t* b) {
    asm volatile("mma.sync.aligned.m16n8k8.row.col.f32.tf32.tf32.f32 "
                 "{%0,%1,%2,%3}, {%4,%5,%6,%7}, {%8,%9}, {%0,%1,%2,%3};"
                 : "+f"(d[0]), "+f"(d[1]), "+f"(d[2]), "+f"(d[3])
                 : "r"(a[0]), "r"(a[1]), "r"(a[2]), "r"(a[3]), "r"(b[0]), "r"(b[1]));
}

// storage position of logical batch row b: pairs (m, m+8) adjacent within 16-blocks
__device__ __forceinline__ int bpos(int b) {
    return (b & ~15) + ((b & 7) * 2) + ((b >> 3) & 1);
}

// ---------------- Kernel 1: x -> g_xT[c][h][w][bpos(b)] (tf32) ---------------
__global__ __launch_bounds__(256)
void prep_x_kernel(const float* __restrict__ x) {
    const int c = blockIdx.x >> 5;
    const int h = blockIdx.x & 31;
    __shared__ float tile[WID * 129];
    const int tid = threadIdx.x;
#pragma unroll
    for (int it = 0; it < 16; it++) {
        const int idx = it * 256 + tid;
        const int b = idx >> 5, w = idx & 31;
        tile[w * 129 + b] = x[(((size_t)b * CI + c) * HGT + h) * WID + w];
    }
    __syncthreads();
#pragma unroll
    for (int it = 0; it < 16; it++) {
        const int idx = it * 256 + tid;
        const int w = idx >> 7, b = idx & 127;
        g_xT[(((size_t)c * HGT + h) * WID + w) * BATCH + bpos(b)] = f2tf32(tile[w * 129 + b]);
    }
}

// ---------------- Kernel 2: main MMA GEMM ------------------------------------
__global__ __launch_bounds__(256, 2)
void lc2d_mma_kernel(const float* __restrict__ wgt) {
    extern __shared__ __align__(16) char dyns[];
    __shared__ int rowsAll[NCHUNK * KC];

    const uint32_t dynb = smem_u32(dyns);
    const int hw  = blockIdx.x;
    const int h   = hw >> 5;
    const int w   = hw & 31;
    const int tid = threadIdx.x;
    const int wrp = tid >> 5;
    const int lane = tid & 31;

    const int wm = (wrp & 1) * 64;          // M offset
    const int wn = ((wrp >> 1) & 1) * 32;   // N offset
    const int wk = wrp >> 2;                // K-split half

    // ---- precompute kk -> xT row for all chunks --------------------------
    for (int t = tid; t < NCHUNK * KC; t += 256) {
        const int c  = t / 9;
        const int r9 = t - c * 9;
        const int p  = r9 / 3;
        const int q  = r9 - p * 3;
        const int hh = h + p - 1;
        const int ww = w + q - 1;
        rowsAll[t] = (hh < 0 || hh >= HGT || ww < 0 || ww >= WID)
                   ? -1 : ((c * HGT + hh) * WID + ww);
    }
    __syncthreads();

    float acc[4][4][4];
#pragma unroll
    for (int mf = 0; mf < 4; mf++)
#pragma unroll
        for (int nf = 0; nf < 4; nf++)
#pragma unroll
            for (int c = 0; c < 4; c++) acc[mf][nf][c] = 0.0f;

    // ---- per-thread incremental B staging state --------------------------
    // kk = tid & 63 is FIXED across chunks; o = (tid>>6) + 4*it.
    const int kkB = tid & 63;
    int cB = kkB / 9;
    int kB = kkB - cB * 9;
    const float* srcB = wgt + ((size_t)(tid >> 6) * CI + cB) * (HWN * 9)
                            + (size_t)hw * 9 + kB;
    // fixed dst permutation: pairs (k, k+4) adjacent within each 8-group
    const int gB  = kkB >> 3;
    const int iB  = kkB & 7;
    const uint32_t dstB = OFF_B + (uint32_t)(tid >> 6) * BSTRB
                        + (uint32_t)(gB * 8 + (((iB & 3) << 1) | (iB >> 2))) * 4;
    // A staging: b4 = tid&31 fixed, kk = (tid>>5) + 8*it
    const int b4A  = tid & 31;
    const int kk0A = tid >> 5;

    // ---- prefetch chunk j into buffer base sb (advances B state) ---------
    auto prefetch = [&](int j, uint32_t sb) {
        // A: 64kk x 128b, 16B per cp
#pragma unroll
        for (int it = 0; it < 8; it++) {
            const int kk  = kk0A + it * 8;
            const int row = rowsAll[j * KC + kk];
            const float* src = g_xT + (size_t)(row < 0 ? 0 : row) * BATCH + b4A * 4;
            cp16(sb + (uint32_t)kk * ASTRB + (uint32_t)b4A * 16, src, row < 0 ? 0 : 16);
        }
        // B: 64o x 64kk, 4B per cp; o advances by 4 per it (const offsets)
#pragma unroll
        for (int it = 0; it < 16; it++)
            cp4(sb + dstB + (uint32_t)it * (4 * BSTRB),
                srcB + (size_t)it * (4 * CI * HWN * 9));
        // advance B state: kk += 64  =>  c += 7, k += 1 (carry at k==9)
        kB += 1; 
        if (kB == 9) { kB = 0; srcB += (8 * HWN * 9 - 8); }
        else         {         srcB += (7 * HWN * 9 + 1); }
    };

    prefetch(0, dynb);
    CP_COMMIT();

    for (int j = 0; j < NCHUNK; j++) {
        const uint32_t sb = dynb + (uint32_t)(j & 1) * STAGE;
        if (j + 1 < NCHUNK) prefetch(j + 1, dynb + (uint32_t)((j + 1) & 1) * STAGE);
        CP_COMMIT();
        if (j + 1 < NCHUNK) asm volatile("cp.async.wait_group 1;" ::: "memory");
        else                asm volatile("cp.async.wait_group 0;" ::: "memory");
        __syncthreads();

        // ---- compute: this warp's 4 k8-steps -----------------------------
#pragma unroll
        for (int s = 0; s < 4; s++) {
            const int kk0 = wk * 32 + s * 8;
            // A frags via lds64 on paired-b storage: (m, m+8) adjacent
            const uint32_t rA0 = sb + (uint32_t)(kk0 + (lane & 3)) * ASTRB
                               + (uint32_t)wm * 4 + (uint32_t)(lane >> 2) * 8;
            const uint32_t rA1 = rA0 + 4 * ASTRB;   // k+4
            uint32_t a[4][4];
#pragma unroll
            for (int mf = 0; mf < 4; mf++) {
                lds64(rA0 + mf * 64, a[mf][0], a[mf][1]);
                lds64(rA1 + mf * 64, a[mf][2], a[mf][3]);
            }
            const uint32_t rB = sb + OFF_B + (uint32_t)(wn + (lane >> 2)) * BSTRB
                              + (uint32_t)(wk * 4 + s) * 32 + (uint32_t)(lane & 3) * 8;
            uint32_t bb[4][2];
#pragma unroll
            for (int nf = 0; nf < 4; nf++)
                lds64(rB + nf * 8 * BSTRB, bb[nf][0], bb[nf][1]);
#pragma unroll
            for (int mf = 0; mf < 4; mf++)
#pragma unroll
                for (int nf = 0; nf < 4; nf++)
                    mma_tf32(acc[mf][nf], a[mf], bb[nf]);
        }
        __syncthreads();   // chunk consumed; next iter may overwrite this buffer
    }

    // ---- epilogue: K-split reduce via smem, then coalesced store ---------
    float* sOut = reinterpret_cast<float*>(dyns);   // [o][b], stride 132 (logical b)
    if (wk == 1) {
#pragma unroll
        for (int mf = 0; mf < 4; mf++)
#pragma unroll
            for (int nf = 0; nf < 4; nf++)
#pragma unroll
                for (int c = 0; c < 4; c++) {
                    const int b = wm + mf * 16 + (lane >> 2) + ((c & 2) ? 8 : 0);
                    const int o = wn + nf * 8 + ((lane & 3) << 1) + (c & 1);
                    sOut[o * 132 + b] = acc[mf][nf][c];
                }
    }
    __syncthreads();
    if (wk == 0) {
#pragma unroll
        for (int mf = 0; mf < 4; mf++)
#pragma unroll
            for (int nf = 0; nf < 4; nf++)
#pragma unroll
                for (int c = 0; c < 4; c++) {
                    const int b = wm + mf * 16 + (lane >> 2) + ((c & 2) ? 8 : 0);
                    const int o = wn + nf * 8 + ((lane & 3) << 1) + (c & 1);
                    sOut[o * 132 + b] += acc[mf][nf][c];
                }
    }
    __syncthreads();

    float* dst = g_outT + (size_t)hw * (CO * BATCH);
#pragma unroll
    for (int it = 0; it < 8; it++) {
        const int idx = it * 256 + tid;       // 2048 float4
        const int o  = idx >> 5;
        const int b4 = (idx & 31) << 2;
        const float4 v = *reinterpret_cast<const float4*>(sOut + o * 132 + b4);
        *reinterpret_cast<float4*>(dst + o * BATCH + b4) = v;
    }
}

// ---------------- Kernel 3: g_outT[hw][o][b] -> out[b][o][hw] ----------------
__global__ __launch_bounds__(256)
void out_transpose_kernel(float* __restrict__ out) {
    const int o   = blockIdx.x >> 5;
    const int hw0 = (blockIdx.x & 31) * 32;
    __shared__ float tile[BATCH * 33];
    const int tid = threadIdx.x;
#pragma unroll
    for (int it = 0; it < 16; it++) {
        const int idx = it * 256 + tid;
        const int i = idx >> 7, b = idx & 127;
        tile[b * 33 + i] = g_outT[((size_t)(hw0 + i) * CO + o) * BATCH + b];
    }
    __syncthreads();
#pragma unroll
    for (int it = 0; it < 16; it++) {
        const int idx = it * 256 + tid;
        const int b = idx >> 5, i = idx & 31;
        out[((size_t)b * CO + o) * HWN + hw0 + i] = tile[b * 33 + i];
    }
}

// ---------------- launch -----------------------------------------------------
extern "C" void kernel_launch(void* const* d_in, const int* in_sizes, int n_in,
                              void* d_out, int out_size) {
    const float* x   = (const float*)d_in[0];
    const float* wgt = (const float*)d_in[1];
    float* out = (float*)d_out;
    (void)in_sizes; (void)n_in; (void)out_size;

    cudaFuncSetAttribute(lc2d_mma_kernel, cudaFuncAttributeMaxDynamicSharedMemorySize, DYN_BYTES);

    prep_x_kernel<<<CI * HGT, 256>>>(x);
    lc2d_mma_kernel<<<HWN, 256, DYN_BYTES>>>(wgt);
    out_transpose_kernel<<<CO * 32, 256>>>(out);
}

// round 9
// speedup vs baseline: 1.3427x; 1.3427x over previous
#include <cuda_runtime.h>
#include <cuda_fp16.h>
#include <cstdint>

// LocallyConnected2d via single-pass fp16 mma.sync m16n8k16 implicit GEMM.
// out[b,o,h,w] = sum_{c,k} patch(x)[b,c,h,w,k] * W[o,c,h,w,k]
// x: [128,64,32,32] f32   weight: [1,64,64,32,32,9] f32   out: [128,64,32,32] f32
//
// R9: R8 + the missing __syncthreads() between cp.async.wait_group and the
//     B convert loop (convert reads OTHER threads' cp.async results; wait_group
//     alone only orders this thread's copies -> race -> rel_err 2e-2).

#define BATCH 128
#define CI    64
#define CO    64
#define HGT   32
#define WID   32
#define HWN   1024
#define KC    64
#define NCHUNK 9

#define ASTRH  272                  // A fp16 row stride bytes (128 h + 8 pad)
#define BSTRH  144                  // B fp16 row stride bytes (64 h + 8 pad)
#define BSTR32 272                  // B fp32 staging row stride bytes (64 f + 4 pad)
#define OFF_BH  17408               // 64*272
#define OFF_B32 26624               // OFF_BH + 64*144
#define STAGE   44032               // OFF_B32 + 64*272
#define DYN_BYTES (2 * STAGE)

__device__ __half g_xh[CI * HGT * WID * BATCH];  // 8 MB  [c][h][w][b] fp16
__device__ float  g_outT[HWN * CO * BATCH];      // 32 MB [hw][o][b]

// ---------------- helpers ----------------------------------------------------
__device__ __forceinline__ uint32_t smem_u32(const void* p) {
    uint32_t a;
    asm("{ .reg .u64 t; cvta.to.shared.u64 t, %1; cvt.u32.u64 %0, t; }" : "=r"(a) : "l"(p));
    return a;
}
__device__ __forceinline__ void lds64f(uint32_t a, float& x, float& y) {
    asm volatile("ld.shared.v2.f32 {%0,%1}, [%2];" : "=f"(x), "=f"(y) : "r"(a));
}
__device__ __forceinline__ void lds64(uint32_t a, uint32_t& lo, uint32_t& hi) {
    asm volatile("ld.shared.v2.b32 {%0,%1}, [%2];" : "=r"(lo), "=r"(hi) : "r"(a));
}
__device__ __forceinline__ void sts32(uint32_t a, uint32_t v) {
    asm volatile("st.shared.b32 [%0], %1;" :: "r"(a), "r"(v) : "memory");
}
__device__ __forceinline__ void cp16(uint32_t dst, const void* src, int srcbytes) {
    asm volatile("cp.async.cg.shared.global [%0], [%1], 16, %2;"
                 :: "r"(dst), "l"(src), "r"(srcbytes) : "memory");
}
__device__ __forceinline__ void cp4(uint32_t dst, const void* src) {
    asm volatile("cp.async.ca.shared.global [%0], [%1], 4;"
                 :: "r"(dst), "l"(src) : "memory");
}
#define CP_COMMIT() asm volatile("cp.async.commit_group;" ::: "memory")
__device__ __forceinline__ void ldm4t(uint32_t* r, uint32_t addr) {
    asm volatile("ldmatrix.sync.aligned.m8n8.x4.trans.shared.b16 {%0,%1,%2,%3}, [%4];"
                 : "=r"(r[0]), "=r"(r[1]), "=r"(r[2]), "=r"(r[3]) : "r"(addr));
}
__device__ __forceinline__ void mma_f16(float* d, const uint32_t* a, const uint32_t* b) {
    asm volatile("mma.sync.aligned.m16n8k16.row.col.f32.f16.f16.f32 "
                 "{%0,%1,%2,%3}, {%4,%5,%6,%7}, {%8,%9}, {%0,%1,%2,%3};"
                 : "+f"(d[0]), "+f"(d[1]), "+f"(d[2]), "+f"(d[3])
                 : "r"(a[0]), "r"(a[1]), "r"(a[2]), "r"(a[3]), "r"(b[0]), "r"(b[1]));
}

// ---------------- Kernel 1: x -> g_xh[c][h][w][b] fp16 -----------------------
__global__ __launch_bounds__(256)
void prep_x_kernel(const float* __restrict__ x) {
    const int c = blockIdx.x >> 5;
    const int h = blockIdx.x & 31;
    __shared__ float tile[WID * 129];
    const int tid = threadIdx.x;
#pragma unroll
    for (int it = 0; it < 16; it++) {
        const int idx = it * 256 + tid;
        const int b = idx >> 5, w = idx & 31;
        tile[w * 129 + b] = x[(((size_t)b * CI + c) * HGT + h) * WID + w];
    }
    __syncthreads();
#pragma unroll
    for (int it = 0; it < 16; it++) {
        const int idx = it * 256 + tid;
        const int w = idx >> 7, b = idx & 127;
        g_xh[(((size_t)c * HGT + h) * WID + w) * BATCH + b] = __float2half_rn(tile[w * 129 + b]);
    }
}

// ---------------- Kernel 2: main MMA GEMM ------------------------------------
__global__ __launch_bounds__(256, 2)
void lc2d_mma_kernel(const float* __restrict__ wgt) {
    extern __shared__ __align__(16) char dyns[];
    __shared__ int rowsAll[NCHUNK * KC];

    const uint32_t dynb = smem_u32(dyns);
    const int hw  = blockIdx.x;
    const int h   = hw >> 5;
    const int w   = hw & 31;
    const int tid = threadIdx.x;
    const int wrp = tid >> 5;
    const int lane = tid & 31;

    const int wm = (wrp & 1) * 64;          // M offset
    const int wn = ((wrp >> 1) & 1) * 32;   // N offset
    const int wk = wrp >> 2;                // K-split half (kk 0..31 vs 32..63)

    // ldmatrix lane address components ([kk][b] storage, trans)
    const int lm_r    = lane & 7;
    const int lm_koff = (lane & 16) ? 8 : 0;
    const int lm_moff = (lane & 8) ? 8 : 0;

    // ---- precompute kk -> x row for all chunks ---------------------------
    for (int t = tid; t < NCHUNK * KC; t += 256) {
        const int c  = t / 9;
        const int r9 = t - c * 9;
        const int p  = r9 / 3;
        const int q  = r9 - p * 3;
        const int hh = h + p - 1;
        const int ww = w + q - 1;
        rowsAll[t] = (hh < 0 || hh >= HGT || ww < 0 || ww >= WID)
                   ? -1 : ((c * HGT + hh) * WID + ww);
    }
    __syncthreads();

    float acc[4][4][4];
#pragma unroll
    for (int mf = 0; mf < 4; mf++)
#pragma unroll
        for (int nf = 0; nf < 4; nf++)
#pragma unroll
            for (int c = 0; c < 4; c++) acc[mf][nf][c] = 0.0f;

    // ---- incremental B staging state (kk = tid&63 fixed across chunks) ----
    const int kkB = tid & 63;
    int kB = kkB % 9;
    const float* srcB = wgt + ((size_t)(tid >> 6) * CI + kkB / 9) * (HWN * 9)
                            + (size_t)hw * 9 + kB;
    const uint32_t dstB = OFF_B32 + (uint32_t)(tid >> 6) * BSTR32 + (uint32_t)kkB * 4;
    // A staging: seg = tid&15 fixed, kk = (tid>>4) + 16*it
    const int segA = tid & 15;
    const int kk0A = tid >> 4;

    auto prefetch = [&](int j, uint32_t sb) {
        // A: 64kk x 128b fp16 = 1024 x 16B
#pragma unroll
        for (int it = 0; it < 4; it++) {
            const int kk  = kk0A + it * 16;
            const int row = rowsAll[j * KC + kk];
            const __half* src = g_xh + (size_t)(row < 0 ? 0 : row) * BATCH + segA * 8;
            cp16(sb + (uint32_t)kk * ASTRH + (uint32_t)segA * 16, src, row < 0 ? 0 : 16);
        }
        // B fp32: 64o x 64kk = 4096 x 4B, linear dst
#pragma unroll
        for (int it = 0; it < 16; it++)
            cp4(sb + dstB + (uint32_t)it * (4 * BSTR32),
                srcB + (size_t)it * (4 * CI * HWN * 9));
        // advance: kk += 64  =>  k += 1 with carry at 9
        kB += 1;
        if (kB == 9) { kB = 0; srcB += (8 * HWN * 9 - 8); }
        else         {         srcB += (7 * HWN * 9 + 1); }
    };

    prefetch(0, dynb);
    CP_COMMIT();

    for (int j = 0; j < NCHUNK; j++) {
        const uint32_t sb = dynb + (uint32_t)(j & 1) * STAGE;
        if (j + 1 < NCHUNK) prefetch(j + 1, dynb + (uint32_t)((j + 1) & 1) * STAGE);
        CP_COMMIT();
        if (j + 1 < NCHUNK) asm volatile("cp.async.wait_group 1;" ::: "memory");
        else                asm volatile("cp.async.wait_group 0;" ::: "memory");
        __syncthreads();   // R9 FIX: make ALL threads' cp.async results visible
                           // before the convert loop reads cross-thread B32 data.

        // ---- convert B fp32 -> fp16 tile, word-permuted ------------------
        // fp16 row: 4 groups of 16 k; within group, 4B words [w0,w4,w1,w5,w2,w6,w3,w7]
#pragma unroll
        for (int it = 0; it < 8; it++) {
            const int u  = it * 256 + tid;
            const int o  = u >> 5;
            const int wi = u & 31;              // word index: k pair (2wi, 2wi+1)
            float f0, f1;
            lds64f(sb + OFF_B32 + (uint32_t)o * BSTR32 + (uint32_t)wi * 8, f0, f1);
            const __half2 hv = __floats2half2_rn(f0, f1);   // lo = f0
            const int g   = wi >> 3;
            const int win = wi & 7;
            const int np  = ((win & 3) << 1) | (win >> 2);
            sts32(sb + OFF_BH + (uint32_t)o * BSTRH + (uint32_t)(g * 32 + np * 4),
                  *reinterpret_cast<const uint32_t*>(&hv));
        }
        __syncthreads();

        // ---- compute: this warp's 2 k16-steps ----------------------------
#pragma unroll
        for (int s = 0; s < 2; s++) {
            const int kk0 = wk * 32 + s * 16;
            const uint32_t arow = sb + (uint32_t)(kk0 + lm_koff + lm_r) * ASTRH;
            uint32_t a[4][4];
#pragma unroll
            for (int mf = 0; mf < 4; mf++)
                ldm4t(a[mf], arow + (uint32_t)(wm + mf * 16 + lm_moff) * 2);
            const uint32_t rB = sb + OFF_BH + (uint32_t)(wn + (lane >> 2)) * BSTRH
                              + (uint32_t)((kk0 >> 4) * 32) + (uint32_t)(lane & 3) * 8;
            uint32_t bb[4][2];
#pragma unroll
            for (int nf = 0; nf < 4; nf++)
                lds64(rB + (uint32_t)nf * (8 * BSTRH), bb[nf][0], bb[nf][1]);
#pragma unroll
            for (int mf = 0; mf < 4; mf++)
#pragma unroll
                for (int nf = 0; nf < 4; nf++)
                    mma_f16(acc[mf][nf], a[mf], bb[nf]);
        }
        __syncthreads();   // chunk consumed; next iter may overwrite buffers
    }

    // ---- epilogue: K-split reduce via smem, coalesced store --------------
    float* sOut = reinterpret_cast<float*>(dyns);   // [o][b], stride 132
    if (wk == 1) {
#pragma unroll
        for (int mf = 0; mf < 4; mf++)
#pragma unroll
            for (int nf = 0; nf < 4; nf++)
#pragma unroll
                for (int c = 0; c < 4; c++) {
                    const int b = wm + mf * 16 + (lane >> 2) + ((c & 2) ? 8 : 0);
                    const int o = wn + nf * 8 + ((lane & 3) << 1) + (c & 1);
                    sOut[o * 132 + b] = acc[mf][nf][c];
                }
    }
    __syncthreads();
    if (wk == 0) {
#pragma unroll
        for (int mf = 0; mf < 4; mf++)
#pragma unroll
            for (int nf = 0; nf < 4; nf++)
#pragma unroll
                for (int c = 0; c < 4; c++) {
                    const int b = wm + mf * 16 + (lane >> 2) + ((c & 2) ? 8 : 0);
                    const int o = wn + nf * 8 + ((lane & 3) << 1) + (c & 1);
                    sOut[o * 132 + b] += acc[mf][nf][c];
                }
    }
    __syncthreads();

    float* dst = g_outT + (size_t)hw * (CO * BATCH);
#pragma unroll
    for (int it = 0; it < 8; it++) {
        const int idx = it * 256 + tid;       // 2048 float4
        const int o  = idx >> 5;
        const int b4 = (idx & 31) << 2;
        const float4 v = *reinterpret_cast<const float4*>(sOut + o * 132 + b4);
        *reinterpret_cast<float4*>(dst + o * BATCH + b4) = v;
    }
}

// ---------------- Kernel 3: g_outT[hw][o][b] -> out[b][o][hw] ----------------
__global__ __launch_bounds__(256)
void out_transpose_kernel(float* __restrict__ out) {
    const int o   = blockIdx.x >> 5;
    const int hw0 = (blockIdx.x & 31) * 32;
    __shared__ float tile[BATCH * 33];
    const int tid = threadIdx.x;
#pragma unroll
    for (int it = 0; it < 16; it++) {
        const int idx = it * 256 + tid;
        const int i = idx >> 7, b = idx & 127;
        tile[b * 33 + i] = g_outT[((size_t)(hw0 + i) * CO + o) * BATCH + b];
    }
    __syncthreads();
#pragma unroll
    for (int it = 0; it < 16; it++) {
        const int idx = it * 256 + tid;
        const int b = idx >> 5, i = idx & 31;
        out[((size_t)b * CO + o) * HWN + hw0 + i] = tile[b * 33 + i];
    }
}

// ---------------- launch -----------------------------------------------------
extern "C" void kernel_launch(void* const* d_in, const int* in_sizes, int n_in,
                              void* d_out, int out_size) {
    const float* x   = (const float*)d_in[0];
    const float* wgt = (const float*)d_in[1];
    float* out = (float*)d_out;
    (void)in_sizes; (void)n_in; (void)out_size;

    cudaFuncSetAttribute(lc2d_mma_kernel, cudaFuncAttributeMaxDynamicSharedMemorySize, DYN_BYTES);

    prep_x_kernel<<<CI * HGT, 256>>>(x);
    lc2d_mma_kernel<<<HWN, 256, DYN_BYTES>>>(wgt);
    out_transpose_kernel<<<CO * 32, 256>>>(out);
}